// round 14
// baseline (speedup 1.0000x reference)
#include <cuda_runtime.h>

#define THREADS   512
#define MROWS     16          // batch rows per CTA (TM=16)
#define DIMV      128         // DATA + AUG
#define WIDTHV    256
#define DATAV     64
#define BATCH     2048
#define TSTEPS    128
#define SUBSTEPS  4
#define MD        (MROWS*DIMV)    // 2048
#define GRIDN     (BATCH/MROWS)   // 128

typedef unsigned long long ull;

// packed fp32x2 FMA: d = a*b + d
#define FMA2(d, a, b) asm("fma.rn.f32x2 %0, %1, %2, %0;" : "+l"(d) : "l"(a), "l"(b))
#define PACK2(d, s)   asm("mov.b64 %0, {%1, %1};" : "=l"(d) : "r"(s))

// k-major (transposed) weight copies
static __device__ float g_W1t[DIMV * WIDTHV + 16];    // [k<128][j<256]
static __device__ float g_W2t[WIDTHV * WIDTHV + 16];  // [k<256][j<256]
static __device__ float g_W3t[WIDTHV * DIMV + 16];    // [k<256][j<128]

__global__ void transpose_weights(const float* __restrict__ W1,
                                  const float* __restrict__ W2,
                                  const float* __restrict__ W3)
{
    int stride = gridDim.x * blockDim.x;
    int i0 = blockIdx.x * blockDim.x + threadIdx.x;
    for (int t = i0; t < WIDTHV * DIMV; t += stride) {       // W1[j<256][k<128]
        int j = t >> 7, k = t & 127;
        g_W1t[k * WIDTHV + j] = W1[t];
    }
    for (int t = i0; t < WIDTHV * WIDTHV; t += stride) {     // W2[j<256][k<256]
        int j = t >> 8, k = t & 255;
        g_W2t[k * WIDTHV + j] = W2[t];
    }
    for (int t = i0; t < DIMV * WIDTHV; t += stride) {       // W3[j<128][k<256]
        int j = t >> 8, k = t & 255;
        g_W3t[k * DIMV + j] = W3[t];
    }
}

// ---------------------------------------------------------------------------
// Hidden layer (N=256): out[j][m] = relu( sum_k in[k][m]*Wt[k][j] + b[j] )
// Channel-major acts [k][16]: LDS are warp broadcasts, rows f32x2-paired.
// TN=4 cols/thread (float4 weight LDG), TM=16 rows (8 f32x2), G=8 k-groups
// (g = tid>>6, warp-uniform). Partials: 64 scalar floats/writer, stride-65
// rows -> (lane*65+idx) mod 32 = lane+idx: conflict-free STS.32.
// NOTE: act and outp may alias (h1 in-place): all act reads complete before
// the partial-store __syncthreads; outp writes happen after it.
// ---------------------------------------------------------------------------
template<int K, bool RELU>
__device__ __forceinline__ void layer_hidden(const float* act,
                                             float* outp,
                                             const float* __restrict__ Wt,
                                             const float* __restrict__ bias,
                                             float* __restrict__ red, int tid)
{
    constexpr int CT = 64;           // WIDTHV/4 column-threads
    constexpr int G  = THREADS / CT; // 8
    constexpr int KR = K / G;
    const int g  = tid >> 6;         // warp-uniform (CT=64 = 2 warps)
    const int ct = tid & 63;
    const int k0 = g * KR;

    ull acc[8][4];
#pragma unroll
    for (int p = 0; p < 8; ++p)
#pragma unroll
        for (int c = 0; c < 4; ++c) acc[p][c] = 0ull;

    const float4* wp = reinterpret_cast<const float4*>(Wt) + ct;  // lane-contig

#pragma unroll 2
    for (int k = k0; k < k0 + KR; ++k) {
        float4 w = __ldg(wp + k * CT);
        ull wd0, wd1, wd2, wd3;
        PACK2(wd0, __float_as_uint(w.x));
        PACK2(wd1, __float_as_uint(w.y));
        PACK2(wd2, __float_as_uint(w.z));
        PACK2(wd3, __float_as_uint(w.w));

        const ulonglong2* ap = reinterpret_cast<const ulonglong2*>(act + k * MROWS);
        ulonglong2 a0 = ap[0], a1 = ap[1], a2 = ap[2], a3 = ap[3];  // broadcast
        ull av[8] = { a0.x, a0.y, a1.x, a1.y, a2.x, a2.y, a3.x, a3.y };

#pragma unroll
        for (int p = 0; p < 8; ++p) {
            FMA2(acc[p][0], av[p], wd0);
            FMA2(acc[p][1], av[p], wd1);
            FMA2(acc[p][2], av[p], wd2);
            FMA2(acc[p][3], av[p], wd3);
        }
    }

    {   // 64 scalar partial stores, stride-65 writer rows
        float* rr = red + tid * 65;
#pragma unroll
        for (int c = 0; c < 4; ++c)
#pragma unroll
            for (int p = 0; p < 8; ++p) {
                float2 v = *reinterpret_cast<float2*>(&acc[p][c]);
                rr[c * 16 + 2 * p]     = v.x;
                rr[c * 16 + 2 * p + 1] = v.y;
            }
    }
    __syncthreads();

    // reduce G=8 partials + bias + relu; outputs linear in [j][m]
#pragma unroll
    for (int r = 0; r < (WIDTHV * MROWS) / THREADS; ++r) {   // 8 iters
        int o  = tid + r * THREADS;
        int jj = o >> 4, mm = o & 15;
        int woff = (jj >> 2) * 65 + (jj & 3) * 16 + mm;
        float s = bias[jj];
#pragma unroll
        for (int gg = 0; gg < G; ++gg)
            s += red[gg * CT * 65 + woff];
        outp[o] = RELU ? fmaxf(s, 0.0f) : s;
    }
    __syncthreads();
}

// ---------------------------------------------------------------------------
// Output layer (N=128, K=256): TN=4 -> CT=32, G=16, KR=16. FUSED RK combine
// epilogue: reduce writes k_{NS-1}[o] and dst[o] = y[o] + dt*sum c[s]*k_s[o].
// ---------------------------------------------------------------------------
template<int NS>
__device__ __forceinline__ void layer_out_fused(const float* __restrict__ h2,
                                                float* __restrict__ ks,
                                                const float* __restrict__ y,
                                                float* dst,
                                                const float* __restrict__ bias,
                                                float* __restrict__ red,
                                                float dt, const float* cf, int tid)
{
    constexpr int CT = 32;
    constexpr int G  = 16;
    constexpr int KR = WIDTHV / G;   // 16
    const int g  = tid >> 5;         // = warp id, uniform
    const int ct = tid & 31;
    const int k0 = g * KR;

    ull acc[8][4];
#pragma unroll
    for (int p = 0; p < 8; ++p)
#pragma unroll
        for (int c = 0; c < 4; ++c) acc[p][c] = 0ull;

    const float4* wp = reinterpret_cast<const float4*>(g_W3t) + ct;

#pragma unroll 2
    for (int k = k0; k < k0 + KR; ++k) {
        float4 w = __ldg(wp + k * CT);
        ull wd0, wd1, wd2, wd3;
        PACK2(wd0, __float_as_uint(w.x));
        PACK2(wd1, __float_as_uint(w.y));
        PACK2(wd2, __float_as_uint(w.z));
        PACK2(wd3, __float_as_uint(w.w));

        const ulonglong2* ap = reinterpret_cast<const ulonglong2*>(h2 + k * MROWS);
        ulonglong2 a0 = ap[0], a1 = ap[1], a2 = ap[2], a3 = ap[3];
        ull av[8] = { a0.x, a0.y, a1.x, a1.y, a2.x, a2.y, a3.x, a3.y };

#pragma unroll
        for (int p = 0; p < 8; ++p) {
            FMA2(acc[p][0], av[p], wd0);
            FMA2(acc[p][1], av[p], wd1);
            FMA2(acc[p][2], av[p], wd2);
            FMA2(acc[p][3], av[p], wd3);
        }
    }

    {
        float* rr = red + tid * 65;
#pragma unroll
        for (int c = 0; c < 4; ++c)
#pragma unroll
            for (int p = 0; p < 8; ++p) {
                float2 v = *reinterpret_cast<float2*>(&acc[p][c]);
                rr[c * 16 + 2 * p]     = v.x;
                rr[c * 16 + 2 * p + 1] = v.y;
            }
    }
    __syncthreads();

    float dtc[NS];
#pragma unroll
    for (int ss = 0; ss < NS; ++ss) dtc[ss] = dt * cf[ss];

    // reduce 16 partials + bias -> k; fused RK combine; [j][m] linear
#pragma unroll
    for (int r = 0; r < (DIMV * MROWS) / THREADS; ++r) {  // 4 iters
        int o  = tid + r * THREADS;
        int jj = o >> 4, mm = o & 15;
        int woff = (jj >> 2) * 65 + (jj & 3) * 16 + mm;
        float s = bias[jj];
#pragma unroll
        for (int gg = 0; gg < G; ++gg)
            s += red[gg * CT * 65 + woff];
        ks[(NS - 1) * MD + o] = s;

        float v = fmaf(dtc[NS - 1], s, y[o]);
#pragma unroll
        for (int ss = 0; ss < NS - 1; ++ss) {
            if (NS == 6 && ss == 1) continue;   // cb[1] == 0
            v = fmaf(dtc[ss], ks[ss * MD + o], v);
        }
        dst[o] = v;
    }
    __syncthreads();
}

// write data channels (first 64) of all 16 rows for save time t (coalesced)
__device__ __forceinline__ void save_state(const float* __restrict__ y,
                                           float* __restrict__ out,
                                           int base, int t, int tid)
{
#pragma unroll
    for (int r = 0; r < (MROWS * DATAV) / THREADS; ++r) {   // 2 iters
        int i = tid + r * THREADS;
        int m = i >> 6, c = i & 63;
        out[((size_t)t * BATCH + base + m) * DATAV + c] = y[c * MROWS + m];
    }
}

extern "C" __global__ void __launch_bounds__(THREADS, 1)
anode_kernel(const float* __restrict__ ts, const float* __restrict__ y0,
             const float* __restrict__ b1, const float* __restrict__ b2,
             const float* __restrict__ b3,
             float* __restrict__ out, int out_size)
{
    extern __shared__ float sm[];
    float* tssm = sm;                        // 128
    float* b1s  = tssm + 128;                // 256
    float* b2s  = b1s + 256;                 // 256
    float* b3s  = b2s + 256;                 // 128
    float* y    = b3s + 128;                 // 2048
    float* h1   = y    + MD;                 // 4096 (h2 aliases h1: in-place)
    float* ks   = h1   + MROWS * WIDTHV;     // 6*MD = 12288
    float* ytmp = ks   + 5 * MD;             // ALIAS of ks[5]: ks[5] is only
                                             // written in stage 6, after ytmp
                                             // is dead (last read: stage-6 L1)
    float* red  = ks   + 6 * MD;             // 512*65 = 33280
    // total: 768+2048+4096+12288+33280 = 52480 floats = 209,920 B

    const int tid  = threadIdx.x;
    const int base = blockIdx.x * MROWS;

    if (tid < TSTEPS) tssm[tid] = ts[tid];
    if (tid < WIDTHV) { b1s[tid] = b1[tid]; b2s[tid] = b2[tid]; }
    if (tid < DIMV)   b3s[tid] = b3[tid];

    // load batch tile, transposing to [channel][m]
    {
        int m  = tid & 15;
        int c4 = (tid >> 4) << 2;   // 32 groups * 4 = DIMV channels
        float4 v = *reinterpret_cast<const float4*>(y0 + (size_t)(base + m) * DIMV + c4);
        y[(c4 + 0) * MROWS + m] = v.x;
        y[(c4 + 1) * MROWS + m] = v.y;
        y[(c4 + 2) * MROWS + m] = v.z;
        y[(c4 + 3) * MROWS + m] = v.w;
    }
    __syncthreads();

    save_state(y, out, base, 0, tid);

    // Dopri5 tableau rows (combine coefficients applied after each eval)
    const float c2_[1] = {0.2f};
    const float c3_[2] = {3.f/40.f, 9.f/40.f};
    const float c4_[3] = {44.f/45.f, -56.f/15.f, 32.f/9.f};
    const float c5_[4] = {19372.f/6561.f, -25360.f/2187.f, 64448.f/6561.f, -212.f/729.f};
    const float c6_[5] = {9017.f/3168.f, -355.f/33.f, 46732.f/5247.f, 49.f/176.f, -5103.f/18656.f};
    const float cb_[6] = {35.f/384.f, 0.f, 500.f/1113.f, 125.f/192.f, -2187.f/6784.f, 11.f/84.f};

#pragma unroll 1
    for (int t = 1; t < TSTEPS; ++t) {
        float dt = (tssm[t] - tssm[t - 1]) * (1.0f / SUBSTEPS);
#pragma unroll 1
        for (int s = 0; s < SUBSTEPS; ++s) {
            layer_hidden<DIMV,   true>(y,    h1, g_W1t, b1s, red, tid);
            layer_hidden<WIDTHV, true>(h1,   h1, g_W2t, b2s, red, tid);
            layer_out_fused<1>(h1, ks, y, ytmp, b3s, red, dt, c2_, tid);

            layer_hidden<DIMV,   true>(ytmp, h1, g_W1t, b1s, red, tid);
            layer_hidden<WIDTHV, true>(h1,   h1, g_W2t, b2s, red, tid);
            layer_out_fused<2>(h1, ks, y, ytmp, b3s, red, dt, c3_, tid);

            layer_hidden<DIMV,   true>(ytmp, h1, g_W1t, b1s, red, tid);
            layer_hidden<WIDTHV, true>(h1,   h1, g_W2t, b2s, red, tid);
            layer_out_fused<3>(h1, ks, y, ytmp, b3s, red, dt, c4_, tid);

            layer_hidden<DIMV,   true>(ytmp, h1, g_W1t, b1s, red, tid);
            layer_hidden<WIDTHV, true>(h1,   h1, g_W2t, b2s, red, tid);
            layer_out_fused<4>(h1, ks, y, ytmp, b3s, red, dt, c5_, tid);

            layer_hidden<DIMV,   true>(ytmp, h1, g_W1t, b1s, red, tid);
            layer_hidden<WIDTHV, true>(h1,   h1, g_W2t, b2s, red, tid);
            layer_out_fused<5>(h1, ks, y, ytmp, b3s, red, dt, c6_, tid);

            layer_hidden<DIMV,   true>(ytmp, h1, g_W1t, b1s, red, tid);
            layer_hidden<WIDTHV, true>(h1,   h1, g_W2t, b2s, red, tid);
            layer_out_fused<6>(h1, ks, y, y,    b3s, red, dt, cb_, tid);
        }
        save_state(y, out, base, t, tid);
    }

    // second reference output: num_steps = (T-1)*SUBSTEPS = 508
    if (blockIdx.x == 0 && tid == 0) {
        const long long TOT = (long long)TSTEPS * BATCH * DATAV;
        for (long long i = TOT; i < (long long)out_size; ++i)
            out[i] = 508.0f;
    }
}

extern "C" void kernel_launch(void* const* d_in, const int* in_sizes, int n_in,
                              void* d_out, int out_size)
{
    const float* ts = (const float*)d_in[0];
    const float* y0 = (const float*)d_in[1];
    const float* W1 = (const float*)d_in[2];
    const float* b1 = (const float*)d_in[3];
    const float* W2 = (const float*)d_in[4];
    const float* b2 = (const float*)d_in[5];
    const float* W3 = (const float*)d_in[6];
    const float* b3 = (const float*)d_in[7];
    float* out = (float*)d_out;

    transpose_weights<<<256, 256>>>(W1, W2, W3);

    const int smem_bytes = (768 + MD + MROWS * WIDTHV + 6 * MD + THREADS * 65)
                           * (int)sizeof(float);   // 209,920 B
    cudaFuncSetAttribute(anode_kernel,
                         cudaFuncAttributeMaxDynamicSharedMemorySize, smem_bytes);

    anode_kernel<<<GRIDN, THREADS, smem_bytes>>>(ts, y0, b1, b2, b3, out, out_size);
}

// round 15
// speedup vs baseline: 1.0309x; 1.0309x over previous
#include <cuda_runtime.h>

#define THREADS   1024
#define MROWS     16          // batch rows per CTA (TM=16 is load-bearing)
#define DIMV      128         // DATA + AUG
#define WIDTHV    256
#define DATAV     64
#define BATCH     2048
#define TSTEPS    128
#define SUBSTEPS  4
#define MD        (MROWS*DIMV)    // 2048
#define GRIDN     (BATCH/MROWS)   // 128

typedef unsigned long long ull;

// packed fp32x2 FMA: d = a*b + d
#define FMA2(d, a, b) asm("fma.rn.f32x2 %0, %1, %2, %0;" : "+l"(d) : "l"(a), "l"(b))
#define PACK2(d, s)   asm("mov.b64 %0, {%1, %1};" : "=l"(d) : "r"(s))

// k-major (transposed) weight copies
static __device__ float g_W1t[DIMV * WIDTHV + 16];    // [k<128][j<256]
static __device__ float g_W2t[WIDTHV * WIDTHV + 16];  // [k<256][j<256]
static __device__ float g_W3t[WIDTHV * DIMV + 16];    // [k<256][j<128]

__global__ void transpose_weights(const float* __restrict__ W1,
                                  const float* __restrict__ W2,
                                  const float* __restrict__ W3)
{
    int stride = gridDim.x * blockDim.x;
    int i0 = blockIdx.x * blockDim.x + threadIdx.x;
    for (int t = i0; t < WIDTHV * DIMV; t += stride) {       // W1[j<256][k<128]
        int j = t >> 7, k = t & 127;
        g_W1t[k * WIDTHV + j] = W1[t];
    }
    for (int t = i0; t < WIDTHV * WIDTHV; t += stride) {     // W2[j<256][k<256]
        int j = t >> 8, k = t & 255;
        g_W2t[k * WIDTHV + j] = W2[t];
    }
    for (int t = i0; t < DIMV * WIDTHV; t += stride) {       // W3[j<128][k<256]
        int j = t >> 8, k = t & 255;
        g_W3t[k * DIMV + j] = W3[t];
    }
}

// ---------------------------------------------------------------------------
// Hidden layer (N=256): out[j][m] = relu( sum_k in[k][m]*Wt[k][j] + b[j] )
// Channel-major acts [k][16]: LDS are warp broadcasts, rows f32x2-paired.
// TN=2 cols/thread, TM=16 rows (8 f32x2). 1024 threads: CT=128 column-
// threads, G=8 k-groups (g = tid>>7, warp-uniform). Partials: 32 scalar
// floats per writer, stride-33 rows (33 odd -> conflict-free STS.32).
// act/outp may alias (in-place): act reads all complete before the partial-
// store __syncthreads; outp writes happen after it.
// ---------------------------------------------------------------------------
template<int K>
__device__ __forceinline__ void layer256(const float* act,
                                         float* outp,
                                         const float* __restrict__ Wt,
                                         const float* __restrict__ bias,
                                         float* __restrict__ red, int tid)
{
    constexpr int CT = 128;          // N/2
    constexpr int G  = THREADS / CT; // 8
    constexpr int KR = K / G;        // 16 (K=128) / 32 (K=256)
    const int g  = tid >> 7;         // warp-uniform (CT = 4 warps)
    const int ct = tid & 127;
    const int k0 = g * KR;

    ull acc[8][2];
#pragma unroll
    for (int p = 0; p < 8; ++p) { acc[p][0] = 0ull; acc[p][1] = 0ull; }

    const float2* wp = reinterpret_cast<const float2*>(Wt) + ct;

#pragma unroll 4
    for (int k = k0; k < k0 + KR; ++k) {
        float2 w = __ldg(wp + k * CT);
        ull wd0, wd1;
        PACK2(wd0, __float_as_uint(w.x));
        PACK2(wd1, __float_as_uint(w.y));

        const ulonglong2* ap = reinterpret_cast<const ulonglong2*>(act + k * MROWS);
        ulonglong2 a0 = ap[0], a1 = ap[1], a2 = ap[2], a3 = ap[3];  // broadcast
        ull av[8] = { a0.x, a0.y, a1.x, a1.y, a2.x, a2.y, a3.x, a3.y };

#pragma unroll
        for (int p = 0; p < 8; ++p) {
            FMA2(acc[p][0], av[p], wd0);
            FMA2(acc[p][1], av[p], wd1);
        }
    }

    {   // 32 scalar partial stores, stride-33 writer rows
        float* rr = red + tid * 33;
#pragma unroll
        for (int c = 0; c < 2; ++c)
#pragma unroll
            for (int p = 0; p < 8; ++p) {
                float2 v = *reinterpret_cast<float2*>(&acc[p][c]);
                rr[c * 16 + 2 * p]     = v.x;
                rr[c * 16 + 2 * p + 1] = v.y;
            }
    }
    __syncthreads();

    // reduce G=8 partials + bias + relu; outputs linear in [j][m]
#pragma unroll
    for (int r = 0; r < (WIDTHV * MROWS) / THREADS; ++r) {   // 4 iters
        int o  = tid + r * THREADS;
        int jj = o >> 4, mm = o & 15;
        int woff = (jj >> 1) * 33 + (jj & 1) * 16 + mm;
        float s = bias[jj];
#pragma unroll
        for (int gg = 0; gg < G; ++gg)
            s += red[gg * CT * 33 + woff];
        outp[o] = fmaxf(s, 0.0f);
    }
    __syncthreads();
}

// ---------------------------------------------------------------------------
// Output layer (N=128, K=256): CT=64, G=16, KR=16. FUSED RK combine epilogue:
// reduce writes k_{NS-1}[o] and dst[o] = y[o] + dt*sum_{s<NS} c[s]*k_s[o].
// ---------------------------------------------------------------------------
template<int NS>
__device__ __forceinline__ void layer_out_fused(const float* __restrict__ h2,
                                                float* __restrict__ ks,
                                                const float* __restrict__ y,
                                                float* dst,
                                                const float* __restrict__ bias,
                                                float* __restrict__ red,
                                                float dt, const float* cf, int tid)
{
    constexpr int CT = 64;
    constexpr int G  = THREADS / CT; // 16
    constexpr int KR = WIDTHV / G;   // 16
    const int g  = tid >> 6;         // warp-uniform (CT = 2 warps)
    const int ct = tid & 63;
    const int k0 = g * KR;

    ull acc[8][2];
#pragma unroll
    for (int p = 0; p < 8; ++p) { acc[p][0] = 0ull; acc[p][1] = 0ull; }

    const float2* wp = reinterpret_cast<const float2*>(g_W3t) + ct;

#pragma unroll 4
    for (int k = k0; k < k0 + KR; ++k) {
        float2 w = __ldg(wp + k * CT);
        ull wd0, wd1;
        PACK2(wd0, __float_as_uint(w.x));
        PACK2(wd1, __float_as_uint(w.y));

        const ulonglong2* ap = reinterpret_cast<const ulonglong2*>(h2 + k * MROWS);
        ulonglong2 a0 = ap[0], a1 = ap[1], a2 = ap[2], a3 = ap[3];
        ull av[8] = { a0.x, a0.y, a1.x, a1.y, a2.x, a2.y, a3.x, a3.y };

#pragma unroll
        for (int p = 0; p < 8; ++p) {
            FMA2(acc[p][0], av[p], wd0);
            FMA2(acc[p][1], av[p], wd1);
        }
    }

    {
        float* rr = red + tid * 33;
#pragma unroll
        for (int c = 0; c < 2; ++c)
#pragma unroll
            for (int p = 0; p < 8; ++p) {
                float2 v = *reinterpret_cast<float2*>(&acc[p][c]);
                rr[c * 16 + 2 * p]     = v.x;
                rr[c * 16 + 2 * p + 1] = v.y;
            }
    }
    __syncthreads();

    float dtc[NS];
#pragma unroll
    for (int ss = 0; ss < NS; ++ss) dtc[ss] = dt * cf[ss];

    // reduce 16 partials + bias -> k; fused RK combine; [j][m] linear
#pragma unroll
    for (int r = 0; r < (DIMV * MROWS) / THREADS; ++r) {  // 2 iters
        int o  = tid + r * THREADS;
        int jj = o >> 4, mm = o & 15;
        int woff = (jj >> 1) * 33 + (jj & 1) * 16 + mm;
        float s = bias[jj];
#pragma unroll
        for (int gg = 0; gg < G; ++gg)
            s += red[gg * CT * 33 + woff];
        ks[(NS - 1) * MD + o] = s;

        float v = fmaf(dtc[NS - 1], s, y[o]);
#pragma unroll
        for (int ss = 0; ss < NS - 1; ++ss) {
            if (NS == 6 && ss == 1) continue;   // cb[1] == 0
            v = fmaf(dtc[ss], ks[ss * MD + o], v);
        }
        dst[o] = v;
    }
    __syncthreads();
}

// write data channels (first 64) of all 16 rows for save time t (coalesced)
__device__ __forceinline__ void save_state(const float* __restrict__ y,
                                           float* __restrict__ out,
                                           int base, int t, int tid)
{
    // MROWS*DATAV = 1024 = THREADS: one element per thread
    int m = tid >> 6, c = tid & 63;
    out[((size_t)t * BATCH + base + m) * DATAV + c] = y[c * MROWS + m];
}

extern "C" __global__ void __launch_bounds__(THREADS, 1)
anode_kernel(const float* __restrict__ ts, const float* __restrict__ y0,
             const float* __restrict__ b1, const float* __restrict__ b2,
             const float* __restrict__ b3,
             float* __restrict__ out, int out_size)
{
    extern __shared__ float sm[];
    float* tssm = sm;                        // 128
    float* b1s  = tssm + 128;                // 256
    float* b2s  = b1s + 256;                 // 256
    float* b3s  = b2s + 256;                 // 128
    float* y    = b3s + 128;                 // 2048
    float* h1   = y    + MD;                 // 4096 (layer-2 runs in-place)
    float* ks   = h1   + MROWS * WIDTHV;     // 6*MD = 12288
    float* ytmp = ks   + 5 * MD;             // ALIAS of ks[5]: ks[5] only
                                             // written in stage 6, after ytmp
                                             // is dead (last read: stage-6 L1)
    float* red  = ks   + 6 * MD;             // 1024*33 = 33792
    // total: 768+2048+4096+12288+33792 = 52992 floats = 211,968 B

    const int tid  = threadIdx.x;
    const int base = blockIdx.x * MROWS;

    if (tid < TSTEPS) tssm[tid] = ts[tid];
    if (tid < WIDTHV) { b1s[tid] = b1[tid]; b2s[tid] = b2[tid]; }
    if (tid < DIMV)   b3s[tid] = b3[tid];

    // load batch tile, transposing to [channel][m] (1024 threads, 2 floats ea)
    {
        int m  = tid & 15;
        int c2 = (tid >> 4) << 1;   // 64 groups * 2 = DIMV channels
        float2 v = *reinterpret_cast<const float2*>(y0 + (size_t)(base + m) * DIMV + c2);
        y[(c2 + 0) * MROWS + m] = v.x;
        y[(c2 + 1) * MROWS + m] = v.y;
    }
    __syncthreads();

    save_state(y, out, base, 0, tid);

    // Dopri5 tableau rows (combine coefficients applied after each eval)
    const float c2_[1] = {0.2f};
    const float c3_[2] = {3.f/40.f, 9.f/40.f};
    const float c4_[3] = {44.f/45.f, -56.f/15.f, 32.f/9.f};
    const float c5_[4] = {19372.f/6561.f, -25360.f/2187.f, 64448.f/6561.f, -212.f/729.f};
    const float c6_[5] = {9017.f/3168.f, -355.f/33.f, 46732.f/5247.f, 49.f/176.f, -5103.f/18656.f};
    const float cb_[6] = {35.f/384.f, 0.f, 500.f/1113.f, 125.f/192.f, -2187.f/6784.f, 11.f/84.f};

#pragma unroll 1
    for (int t = 1; t < TSTEPS; ++t) {
        float dt = (tssm[t] - tssm[t - 1]) * (1.0f / SUBSTEPS);
#pragma unroll 1
        for (int s = 0; s < SUBSTEPS; ++s) {
            layer256<DIMV>  (y,    h1, g_W1t, b1s, red, tid);
            layer256<WIDTHV>(h1,   h1, g_W2t, b2s, red, tid);
            layer_out_fused<1>(h1, ks, y, ytmp, b3s, red, dt, c2_, tid);

            layer256<DIMV>  (ytmp, h1, g_W1t, b1s, red, tid);
            layer256<WIDTHV>(h1,   h1, g_W2t, b2s, red, tid);
            layer_out_fused<2>(h1, ks, y, ytmp, b3s, red, dt, c3_, tid);

            layer256<DIMV>  (ytmp, h1, g_W1t, b1s, red, tid);
            layer256<WIDTHV>(h1,   h1, g_W2t, b2s, red, tid);
            layer_out_fused<3>(h1, ks, y, ytmp, b3s, red, dt, c4_, tid);

            layer256<DIMV>  (ytmp, h1, g_W1t, b1s, red, tid);
            layer256<WIDTHV>(h1,   h1, g_W2t, b2s, red, tid);
            layer_out_fused<4>(h1, ks, y, ytmp, b3s, red, dt, c5_, tid);

            layer256<DIMV>  (ytmp, h1, g_W1t, b1s, red, tid);
            layer256<WIDTHV>(h1,   h1, g_W2t, b2s, red, tid);
            layer_out_fused<5>(h1, ks, y, ytmp, b3s, red, dt, c6_, tid);

            layer256<DIMV>  (ytmp, h1, g_W1t, b1s, red, tid);
            layer256<WIDTHV>(h1,   h1, g_W2t, b2s, red, tid);
            layer_out_fused<6>(h1, ks, y, y,    b3s, red, dt, cb_, tid);
        }
        save_state(y, out, base, t, tid);
    }

    // second reference output: num_steps = (T-1)*SUBSTEPS = 508
    if (blockIdx.x == 0 && tid == 0) {
        const long long TOT = (long long)TSTEPS * BATCH * DATAV;
        for (long long i = TOT; i < (long long)out_size; ++i)
            out[i] = 508.0f;
    }
}

extern "C" void kernel_launch(void* const* d_in, const int* in_sizes, int n_in,
                              void* d_out, int out_size)
{
    const float* ts = (const float*)d_in[0];
    const float* y0 = (const float*)d_in[1];
    const float* W1 = (const float*)d_in[2];
    const float* b1 = (const float*)d_in[3];
    const float* W2 = (const float*)d_in[4];
    const float* b2 = (const float*)d_in[5];
    const float* W3 = (const float*)d_in[6];
    const float* b3 = (const float*)d_in[7];
    float* out = (float*)d_out;

    transpose_weights<<<256, 256>>>(W1, W2, W3);

    const int smem_bytes = (768 + MD + MROWS * WIDTHV + 6 * MD + THREADS * 33)
                           * (int)sizeof(float);   // 211,968 B
    cudaFuncSetAttribute(anode_kernel,
                         cudaFuncAttributeMaxDynamicSharedMemorySize, smem_bytes);

    anode_kernel<<<GRIDN, THREADS, smem_bytes>>>(ts, y0, b1, b2, b3, out, out_size);
}